// round 1
// baseline (speedup 1.0000x reference)
#include <cuda_runtime.h>
#include <cstdint>
#include <cstdio>

#define B_   64
#define T_   512
#define H_   512
#define E_   128
#define C_   1000
#define G7   (7 * H_)    // 3584
#define OUTW (6 * H_)    // 3072
#define NCTA 128
#define NTHR 128

// ---- device-global scratch (allocation-free rule: static __device__ arrays) ----
__device__ float g_tg[C_ * G7];        // table_gates = emb @ W1 + b   (14.3 MB)
__device__ float g_h[2][H_][B_];       // h_d double buffer, [buf][k][b] layout
__device__ int           g_count;      // grid barrier counter (returns to 0)
__device__ volatile int  g_sense;      // grid barrier sense (even flips/launch -> returns to 0)

// ---- helpers ----
__device__ __forceinline__ float sigf(float x)      { return 1.0f / (1.0f + expf(-x)); }
__device__ __forceinline__ float softplusf(float x) { return fmaxf(x, 0.0f) + log1pf(expf(-fabsf(x))); }

__device__ __forceinline__ void grid_sync(int* sense)
{
    __threadfence();          // make this thread's global writes visible (L2)
    __syncthreads();
    if (threadIdx.x == 0) {
        int s = *sense ^ 1;
        *sense = s;
        if (atomicAdd(&g_count, 1) == (int)gridDim.x - 1) {
            g_count = 0;      // safe: nobody reads it until next barrier, after sense flip
            __threadfence();
            g_sense = s;
        } else {
            while (g_sense != s) { __nanosleep(64); }
            __threadfence();
        }
    }
    __syncthreads();
}

// =====================  Kernel 1: table_gates  =====================
// g_tg[c][col] = sum_e emb[c][e] * W[e][col] + bias[col]
__global__ void tg_kernel(const float* __restrict__ emb,
                          const float* __restrict__ W,
                          const float* __restrict__ bias)
{
    __shared__ float sh_e[16][E_];
    const int col = blockIdx.x * 256 + threadIdx.x;   // 14 * 256 = 3584 exact
    const int c0  = blockIdx.y * 16;

    for (int i = threadIdx.x; i < 16 * E_; i += 256) {
        int ci = i >> 7, e = i & 127;
        int c  = c0 + ci;
        sh_e[ci][e] = (c < C_) ? emb[c * E_ + e] : 0.0f;
    }
    __syncthreads();

    float acc[16];
#pragma unroll
    for (int i = 0; i < 16; ++i) acc[i] = 0.0f;

    for (int e = 0; e < E_; ++e) {
        float wv = W[e * G7 + col];
#pragma unroll
        for (int i = 0; i < 16; ++i) acc[i] = fmaf(sh_e[i][e], wv, acc[i]);
    }
    float bb = bias[col];
#pragma unroll
    for (int i = 0; i < 16; ++i) {
        int c = c0 + i;
        if (c < C_) g_tg[c * G7 + col] = acc[i] + bb;
    }
}

// =====================  Kernel 2: persistent recurrence  =====================
// 128 CTAs x 128 threads. CTA owns j in [4*cta, 4*cta+4) (28 gate columns).
// Thread decomposition: tid = ks*64 + bg*4 + jl ; ks = K-half, bg = b-group(4 b's), jl = local j.
// smem: sh_W [512][28] (resident all steps), sh_h [2][64][64] (per-chunk stage), sh_red [64][7] float4.
#define SMEM_W_F   (512 * 28)          // 14336 floats
#define SMEM_H_F   (2 * 64 * 64)       //  8192 floats
#define SMEM_R_F   (64 * 28)           //  1792 floats
#define SMEM_BYTES ((SMEM_W_F + SMEM_H_F + SMEM_R_F) * 4)   // 97280 B

__global__ void __launch_bounds__(NTHR, 1)
rec_kernel(const int*   __restrict__ marks,
           const float* __restrict__ ts,
           const float* __restrict__ Wc,
           const float* __restrict__ init,
           float*       __restrict__ out)
{
    extern __shared__ float smem[];
    float* sh_W   = smem;                       // [k][g*4+jl]
    float* sh_h   = smem + SMEM_W_F;            // [grp][kl][b]
    float* sh_red = sh_h + SMEM_H_F;            // float4 [r][7]

    const int tid = threadIdx.x;
    const int cta = blockIdx.x;
    const int ks  = tid >> 6;
    const int r   = tid & 63;
    const int bg  = r >> 2;
    const int jl  = r & 3;
    const int j   = cta * 4 + jl;

    // ---- load resident W slice: Wh rows (E..E+511), cols {g*512 + cta*4 + jj} ----
    for (int idx = tid; idx < 512 * 28; idx += NTHR) {
        int k   = idx / 28;
        int c28 = idx - k * 28;
        int g   = c28 >> 2, jj = c28 & 3;
        sh_W[idx] = Wc[(size_t)(E_ + k) * G7 + g * H_ + cta * 4 + jj];
    }

    // ---- init h buffer (this CTA's 4 j rows, all b) : h0 = tanh(init[0:H]) broadcast over b ----
    for (int idx = tid; idx < 4 * 64; idx += NTHR) {
        int jj = idx >> 6, b = idx & 63;
        g_h[0][cta * 4 + jj][b] = tanhf(init[cta * 4 + jj]);
    }

    // ---- output row t=0 : fields [tanh(i0), sig(i5), tanh(i2), tanh(i3), softplus(i4), tanh(i1)] ----
    for (int idx = tid; idx < 4 * 6 * 64; idx += NTHR) {
        int b = idx & 63; int rest = idx >> 6;
        int f = rest % 6; int jj = rest / 6;
        int jg = cta * 4 + jj;
        float v;
        switch (f) {
            case 0:  v = tanhf(init[0 * H_ + jg]);     break;
            case 1:  v = sigf (init[5 * H_ + jg]);     break;
            case 2:  v = tanhf(init[2 * H_ + jg]);     break;
            case 3:  v = tanhf(init[3 * H_ + jg]);     break;
            case 4:  v = softplusf(init[4 * H_ + jg]); break;
            default: v = tanhf(init[1 * H_ + jg]);     break;
        }
        out[(size_t)b * (513 * OUTW) + f * H_ + jg] = v;
    }

    // ---- persistent per-(b,j) state in registers of ks==0 threads ----
    float cd0 = tanhf(init[H_ + j]);
    float cb0 = tanhf(init[2 * H_ + j]);
    float c_dv[4] = {cd0, cd0, cd0, cd0};
    float c_bv[4] = {cb0, cb0, cb0, cb0};

    int sense = 0;
    grid_sync(&sense);   // barrier #1 (total per launch = 512, even -> replay safe)

    for (int t = 0; t < T_; ++t) {
        const float* hcur = &g_h[t & 1][0][0];

        float acc[7][4];
#pragma unroll
        for (int g = 0; g < 7; ++g)
#pragma unroll
            for (int i = 0; i < 4; ++i) acc[g][i] = 0.0f;

        for (int chunk = 0; chunk < 4; ++chunk) {
            __syncthreads();   // previous chunk's sh_h fully consumed
            // stage: 2048 float4 (both K-half groups), coalesced LDG.128 -> conflict-free STS.128
#pragma unroll
            for (int i = 0; i < 16; ++i) {
                int L    = i * NTHR + tid;          // 0..2047
                int b4   = (L & 15) << 2;
                int rest = L >> 4;                  // 0..127
                int kl   = rest & 63;
                int grp  = rest >> 6;
                int kg   = grp * 256 + chunk * 64 + kl;
                float4 v = __ldcg((const float4*)(hcur + kg * 64 + b4));
                *(float4*)(sh_h + (grp << 12) + (kl << 6) + b4) = v;
            }
            __syncthreads();

            const float* wp = sh_W + (ks * 256 + chunk * 64) * 28 + jl;
            const float* hp = sh_h + (ks << 12) + (bg << 2);
#pragma unroll 8
            for (int kl = 0; kl < 64; ++kl) {
                float4 h4 = *(const float4*)hp; hp += 64;
                float hv[4] = {h4.x, h4.y, h4.z, h4.w};
                float wv[7];
#pragma unroll
                for (int g = 0; g < 7; ++g) wv[g] = wp[g * 4];
                wp += 28;
#pragma unroll
                for (int g = 0; g < 7; ++g)
#pragma unroll
                    for (int i = 0; i < 4; ++i)
                        acc[g][i] = fmaf(wv[g], hv[i], acc[g][i]);
            }
        }

        // ---- K-split reduction ----
        __syncthreads();
        if (ks) {
            float4* rb = ((float4*)sh_red) + r * 7;
#pragma unroll
            for (int g = 0; g < 7; ++g)
                rb[g] = make_float4(acc[g][0], acc[g][1], acc[g][2], acc[g][3]);
        }
        __syncthreads();

        if (!ks) {
            const float4* rb = ((const float4*)sh_red) + r * 7;
#pragma unroll
            for (int g = 0; g < 7; ++g) {
                float4 v = rb[g];
                acc[g][0] += v.x; acc[g][1] += v.y; acc[g][2] += v.z; acc[g][3] += v.w;
            }

            float hout[4];
#pragma unroll
            for (int i = 0; i < 4; ++i) {
                int b = bg * 4 + i;
                int m = marks[b * T_ + t];
                const float* tgp = g_tg + (size_t)m * G7 + j;
                float tsv = ts[b * T_ + t];
                float dur = (t > 0) ? (tsv - ts[b * T_ + t - 1]) : tsv;

                float gi  = sigf (acc[0][i] + tgp[0 * H_]);
                float gf  = sigf (acc[1][i] + tgp[1 * H_]);
                float gz  = tanhf(acc[2][i] + tgp[2 * H_]);
                float go  = sigf (acc[3][i] + tgp[3 * H_]);
                float gib = sigf (acc[4][i] + tgp[4 * H_]);
                float gfb = sigf (acc[5][i] + tgp[5 * H_]);
                float gd  = softplusf(acc[6][i] + tgp[6 * H_]);

                float c  = gf * c_dv[i] + gi * gz;
                float cb = gfb * c_bv[i] + gib * gz;
                float cdv = cb + (c - cb) * expf(-gd * dur);
                float hd = go * tanhf(cdv);
                c_dv[i] = cdv; c_bv[i] = cb;

                size_t ob = (size_t)b * (513 * OUTW) + (size_t)(t + 1) * OUTW + j;
                out[ob]          = hd;
                out[ob + 1 * H_] = go;
                out[ob + 2 * H_] = cb;
                out[ob + 3 * H_] = c;
                out[ob + 4 * H_] = gd;
                out[ob + 5 * H_] = cdv;
                hout[i] = hd;
            }
            *(float4*)&g_h[(t + 1) & 1][j][bg * 4] =
                make_float4(hout[0], hout[1], hout[2], hout[3]);
        }

        if (t != T_ - 1) grid_sync(&sense);   // 511 loop barriers + 1 initial = 512 (even)
    }
}

// =====================  launch  =====================
extern "C" void kernel_launch(void* const* d_in, const int* in_sizes, int n_in,
                              void* d_out, int out_size)
{
    const int*   marks = (const int*)  d_in[0];
    const float* ts    = (const float*)d_in[1];
    const float* emb   = (const float*)d_in[2];
    const float* Wc    = (const float*)d_in[3];
    const float* bc    = (const float*)d_in[4];
    const float* init  = (const float*)d_in[5];
    float*       out   = (float*)d_out;

    dim3 g1(G7 / 256, (C_ + 15) / 16);   // (14, 63)
    tg_kernel<<<g1, 256>>>(emb, Wc, bc);

    cudaFuncSetAttribute(rec_kernel, cudaFuncAttributeMaxDynamicSharedMemorySize, SMEM_BYTES);
    rec_kernel<<<NCTA, NTHR, SMEM_BYTES>>>(marks, ts, Wc, init, out);
}